// round 8
// baseline (speedup 1.0000x reference)
#include <cuda_runtime.h>
#include <cuda_fp16.h>
#include <math.h>
#include <stdint.h>

// ---------------------------------------------------------------------------
// HaplotypeEmbedding, fp16 + mma.sync m16n8k16 + ldmatrix.
// 512 threads/block, warp tile 16x64 (32 acc regs) -> occ 2 = 32 warps/SM.
// B tiles staged with cp.async. P has b1/8 folded in. Fast branchless gelu.
// ---------------------------------------------------------------------------

#define L_    8
#define V_    512
#define D_    256
#define HID_  512
#define NOUT_ 256
#define NTOT  131072
#define MTILE 64
#define NBLK  (NTOT / MTILE)   // 2048
#define KCH   64
#define NCH   (HID_ / KCH)     // 8

#define SAH 72
#define SBH 72
#define SA_BUFH (MTILE * SAH)   // 4608 halves
#define SB_BUFH (NOUT_ * SBH)   // 18432 halves

#define SM_TOK_B 0
#define SM_A_B   2048
#define SM_B_B   (SM_A_B + 2 * SA_BUFH * 2)     // 20480
#define SMEM_BYTES (SM_B_B + 2 * SB_BUFH * 2)   // 94208  (x2 blocks = 184 KB)

__device__ __half g_Ph[L_ * V_ * HID_];
__device__ __half g_W2T[NOUT_ * HID_];
__device__ int    g_is64;

__device__ __forceinline__ float gelu_fast(float x) {
    float ax = fabsf(x);
    float z  = 0.70710678118f * ax;
    float t  = __fdividef(1.0f, fmaf(0.47047f, z, 1.0f));
    float q  = fmaf(fmaf(0.7478556f, t, -0.0958798f), t, 0.3480242f) * t;
    float e  = __expf(-z * z);
    float er = fmaf(-q, e, 1.0f);
    return fmaf(0.5f * ax, er, 0.5f * x);
}
__device__ __forceinline__ void mma_f16(float* d, const uint32_t* a,
                                        uint32_t b0, uint32_t b1) {
    asm volatile(
        "mma.sync.aligned.m16n8k16.row.col.f32.f16.f16.f32 "
        "{%0,%1,%2,%3}, {%4,%5,%6,%7}, {%8,%9}, {%0,%1,%2,%3};"
        : "+f"(d[0]), "+f"(d[1]), "+f"(d[2]), "+f"(d[3])
        : "r"(a[0]), "r"(a[1]), "r"(a[2]), "r"(a[3]), "r"(b0), "r"(b1));
}
__device__ __forceinline__ void ldsm4(uint32_t& r0, uint32_t& r1,
                                      uint32_t& r2, uint32_t& r3, uint32_t a) {
    asm volatile("ldmatrix.sync.aligned.m8n8.x4.shared.b16 {%0,%1,%2,%3}, [%4];"
                 : "=r"(r0), "=r"(r1), "=r"(r2), "=r"(r3) : "r"(a));
}
__device__ __forceinline__ void cpasync16(uint32_t dst, const void* src) {
    asm volatile("cp.async.ca.shared.global [%0], [%1], 16;"
                 :: "r"(dst), "l"(src) : "memory");
}

// ---------------------------------------------------------------------------
// Fused prolog: P projection (+ b1/8) + W2 transpose + dtype detect.
__global__ void __launch_bounds__(512) precompute_kernel(
        const float* __restrict__ tables, const float* __restrict__ W1,
        const float* __restrict__ b1, const float* __restrict__ W2,
        const unsigned int* __restrict__ hap) {
    __shared__ float4 sT4[16 * 64];
    const int l  = blockIdx.x >> 5;
    const int v0 = (blockIdx.x & 31) << 4;
    const int j  = threadIdx.x;

    {
        int gidx = blockIdx.x * 512 + j;
        int k = gidx >> 8, n = gidx & 255;
        g_W2T[n * HID_ + k] = __float2half_rn(W2[gidx]);
    }
    if (blockIdx.x == 0 && j == 0) {
        int ok = 1;
        for (int i = 0; i < 64; i++) ok &= (hap[2 * i + 1] == 0u);
        g_is64 = ok;
    }

    const float4* tsrc = (const float4*)(tables + (l * V_ + v0) * D_);
    sT4[j]       = tsrc[j];
    sT4[j + 512] = tsrc[j + 512];
    __syncthreads();

    const float b1v = 0.125f * b1[j];
    float acc[16];
#pragma unroll
    for (int r = 0; r < 16; r++) acc[r] = b1v;
    const float* w1p = W1 + (l * D_) * HID_ + j;
#pragma unroll 4
    for (int dq = 0; dq < 64; dq++) {
        float w0 = w1p[(4 * dq + 0) * HID_];
        float w1 = w1p[(4 * dq + 1) * HID_];
        float w2 = w1p[(4 * dq + 2) * HID_];
        float w3 = w1p[(4 * dq + 3) * HID_];
#pragma unroll
        for (int r = 0; r < 16; r++) {
            float4 t = sT4[r * 64 + dq];
            acc[r] += w0 * t.x; acc[r] += w1 * t.y;
            acc[r] += w2 * t.z; acc[r] += w3 * t.w;
        }
    }
#pragma unroll
    for (int r = 0; r < 16; r++)
        g_Ph[(l * V_ + v0 + r) * HID_ + j] = __float2half_rn(acc[r]);
}

// ---------------------------------------------------------------------------
__global__ void __launch_bounds__(512, 2) main_kernel(
        const unsigned int* __restrict__ hap,
        const float* __restrict__ b2,
        float* __restrict__ out) {
    extern __shared__ char smem[];
    int*    sTok = (int*)(smem + SM_TOK_B);
    __half* sA   = (__half*)(smem + SM_A_B);
    __half* sB   = (__half*)(smem + SM_B_B);
    const uint32_t sbA = (uint32_t)__cvta_generic_to_shared(sA);
    const uint32_t sbB = (uint32_t)__cvta_generic_to_shared(sB);

    const int tid = threadIdx.x, warp = tid >> 5, lane = tid & 31;
    const int is64 = g_is64;

    // tokens (clamped): 512 of them, one per thread
    {
        long gi = (long)blockIdx.x * (MTILE * L_) + tid;
        int v = is64 ? (int)hap[2 * gi] : (int)hap[gi];
        v = v < 0 ? 0 : (v > V_ - 1 ? V_ - 1 : v);
        sTok[tid] = v;
    }

    float acc[8][4];
#pragma unroll
    for (int j = 0; j < 8; j++)
#pragma unroll
        for (int q = 0; q < 4; q++) acc[j][q] = 0.f;

    // producer mapping: row m = tid>>3, 16B segment c = tid&7
    const int pm = tid >> 3;
    const int pc = tid & 7;
    // consumer mapping: 4m x 4n warps, tile 16x64
    const int m0 = (warp >> 2) * 16;
    const int n0 = (warp & 3) * 64;

    const uint32_t aoff0 = ((uint32_t)(m0 + (lane & 15)) * SAH +
                            (uint32_t)(lane >> 4) * 8) * 2;
    const uint32_t boff0 = ((uint32_t)(n0 + (lane >> 4) * 8 + (lane & 7)) * SBH +
                            (uint32_t)((lane >> 3) & 1) * 8) * 2;

    __syncthreads();

    // chunk-invariant gather byte-offsets (P row stride = 1024 B)
    const char* pB = (const char*)g_Ph;
    uint32_t offs[L_];
#pragma unroll
    for (int l = 0; l < L_; l++)
        offs[l] = (uint32_t)(((l * V_ + sTok[pm * L_ + l]) << 10) + pc * 16);

    // ---------------- producer ----------------
    auto produce = [&](int kt, int buf) {
        const uint32_t kb = (uint32_t)(kt * KCH * 2);
        // B tile via cp.async: 4 x 16B per thread
        {
            const uint32_t dstB = sbB + (uint32_t)(buf * SB_BUFH * 2);
            const __half* srcB = g_W2T + kt * KCH + pc * 8;
#pragma unroll
            for (int j = 0; j < 4; j++) {
                int n = (tid >> 3) + j * 64;
                cpasync16(dstB + (uint32_t)(n * SBH + pc * 8) * 2,
                          srcB + n * HID_);
            }
            asm volatile("cp.async.commit_group;" ::: "memory");
        }
        // A row-segment: gelu(sum_l P)
        {
            float2 a0 = make_float2(0.f, 0.f), a1 = a0, a2 = a0, a3 = a0;
#pragma unroll
            for (int lp = 0; lp < 4; lp++) {
                const uint4 u = *(const uint4*)(pB + offs[2 * lp] + kb);
                const uint4 w = *(const uint4*)(pB + offs[2 * lp + 1] + kb);
                __half2 t; float2 p;
                t = __hadd2(*(const __half2*)&u.x, *(const __half2*)&w.x);
                p = __half22float2(t); a0.x += p.x; a0.y += p.y;
                t = __hadd2(*(const __half2*)&u.y, *(const __half2*)&w.y);
                p = __half22float2(t); a1.x += p.x; a1.y += p.y;
                t = __hadd2(*(const __half2*)&u.z, *(const __half2*)&w.z);
                p = __half22float2(t); a2.x += p.x; a2.y += p.y;
                t = __hadd2(*(const __half2*)&u.w, *(const __half2*)&w.w);
                p = __half22float2(t); a3.x += p.x; a3.y += p.y;
            }
            __half2 h0 = __floats2half2_rn(gelu_fast(a0.x), gelu_fast(a0.y));
            __half2 h1 = __floats2half2_rn(gelu_fast(a1.x), gelu_fast(a1.y));
            __half2 h2 = __floats2half2_rn(gelu_fast(a2.x), gelu_fast(a2.y));
            __half2 h3 = __floats2half2_rn(gelu_fast(a3.x), gelu_fast(a3.y));
            uint4 pk;
            pk.x = *(uint32_t*)&h0; pk.y = *(uint32_t*)&h1;
            pk.z = *(uint32_t*)&h2; pk.w = *(uint32_t*)&h3;
            *(uint4*)(sA + buf * SA_BUFH + pm * SAH + pc * 8) = pk;
        }
    };

    // ---------------- consumer ----------------
    auto consume = [&](int buf) {
        const uint32_t aB = sbA + (uint32_t)(buf * SA_BUFH * 2) + aoff0;
        const uint32_t bB = sbB + (uint32_t)(buf * SB_BUFH * 2) + boff0;
#pragma unroll
        for (int ks = 0; ks < 4; ks++) {
            uint32_t a[4];
            ldsm4(a[0], a[1], a[2], a[3], aB + (uint32_t)(ks * 32));
#pragma unroll
            for (int jp = 0; jp < 4; jp++) {
                uint32_t b0, b1r, b2r, b3r;
                ldsm4(b0, b1r, b2r, b3r,
                      bB + (uint32_t)(jp * 16 * SBH * 2) + (uint32_t)(ks * 32));
                mma_f16(acc[2 * jp],     a, b0, b1r);
                mma_f16(acc[2 * jp + 1], a, b2r, b3r);
            }
        }
    };

    // ---------------- pipeline ----------------
    produce(0, 0);
    asm volatile("cp.async.wait_group 0;" ::: "memory");
    __syncthreads();
#pragma unroll 1
    for (int kt = 0; kt < NCH; kt++) {
        const int buf = kt & 1;
        if (kt + 1 < NCH) produce(kt + 1, buf ^ 1);
        consume(buf);
        asm volatile("cp.async.wait_group 0;" ::: "memory");
        __syncthreads();
    }

    // ---------------- epilogue: + b2, store ----------------
    const float2* b2p = (const float2*)b2;
    float2* o2 = (float2*)out;
    size_t r0 = (size_t)blockIdx.x * MTILE + m0 + (lane >> 2);
#pragma unroll
    for (int j = 0; j < 8; j++) {
        int cc = n0 / 2 + 4 * j + (lane & 3);
        float2 bv = __ldg(&b2p[cc]);
        float2 v0 = make_float2(acc[j][0] + bv.x, acc[j][1] + bv.y);
        float2 v1 = make_float2(acc[j][2] + bv.x, acc[j][3] + bv.y);
        o2[r0 * 128 + cc]       = v0;
        o2[(r0 + 8) * 128 + cc] = v1;
    }
}

// ---------------------------------------------------------------------------
extern "C" void kernel_launch(void* const* d_in, const int* in_sizes, int n_in,
                              void* d_out, int out_size) {
    const unsigned int* hap    = (const unsigned int*)d_in[0];
    const float*        tables = (const float*)d_in[1];
    const float*        W1     = (const float*)d_in[2];
    const float*        b1     = (const float*)d_in[3];
    const float*        W2     = (const float*)d_in[4];
    const float*        b2     = (const float*)d_in[5];
    float*              out    = (float*)d_out;

    cudaFuncSetAttribute(main_kernel,
                         cudaFuncAttributeMaxDynamicSharedMemorySize, SMEM_BYTES);

    precompute_kernel<<<L_ * 32, 512>>>(tables, W1, b1, W2, hap);
    main_kernel<<<NBLK, 512, SMEM_BYTES>>>(hap, b2, out);
}

// round 9
// speedup vs baseline: 1.0511x; 1.0511x over previous
#include <cuda_runtime.h>
#include <cuda_fp16.h>
#include <math.h>
#include <stdint.h>

// ---------------------------------------------------------------------------
// HaplotypeEmbedding, fp16 + mma.sync m16n8k16 + ldmatrix.
// 512 thr/block, warp tile 32x32 (min (m+n) under 32-acc-reg cap) -> occ 2.
// cp.async B staging, P has b1/8 folded, fast gelu, FFMA2 prolog.
// ---------------------------------------------------------------------------

#define L_    8
#define V_    512
#define D_    256
#define HID_  512
#define NOUT_ 256
#define NTOT  131072
#define MTILE 64
#define NBLK  (NTOT / MTILE)   // 2048
#define KCH   64
#define NCH   (HID_ / KCH)     // 8

#define SAH 72
#define SBH 72
#define SA_BUFH (MTILE * SAH)   // 4608 halves
#define SB_BUFH (NOUT_ * SBH)   // 18432 halves

#define SM_TOK_B 0
#define SM_A_B   2048
#define SM_B_B   (SM_A_B + 2 * SA_BUFH * 2)     // 20480
#define SMEM_BYTES (SM_B_B + 2 * SB_BUFH * 2)   // 94208

__device__ __half g_Ph[L_ * V_ * HID_];
__device__ __half g_W2T[NOUT_ * HID_];
__device__ int    g_is64;

typedef unsigned long long u64;
__device__ __forceinline__ u64 pack2(float lo, float hi) {
    u64 r; asm("mov.b64 %0, {%1, %2};" : "=l"(r) : "f"(lo), "f"(hi)); return r;
}
__device__ __forceinline__ void unpack2(u64 v, float& lo, float& hi) {
    asm("mov.b64 {%0, %1}, %2;" : "=f"(lo), "=f"(hi) : "l"(v));
}
__device__ __forceinline__ void fma2(u64& c, u64 a, u64 b) {
    asm("fma.rn.f32x2 %0, %1, %2, %0;" : "+l"(c) : "l"(a), "l"(b));
}
__device__ __forceinline__ float gelu_fast(float x) {
    float ax = fabsf(x);
    float z  = 0.70710678118f * ax;
    float t  = __fdividef(1.0f, fmaf(0.47047f, z, 1.0f));
    float q  = fmaf(fmaf(0.7478556f, t, -0.0958798f), t, 0.3480242f) * t;
    float e  = __expf(-z * z);
    float er = fmaf(-q, e, 1.0f);
    return fmaf(0.5f * ax, er, 0.5f * x);
}
__device__ __forceinline__ void mma_f16(float* d, const uint32_t* a,
                                        uint32_t b0, uint32_t b1) {
    asm volatile(
        "mma.sync.aligned.m16n8k16.row.col.f32.f16.f16.f32 "
        "{%0,%1,%2,%3}, {%4,%5,%6,%7}, {%8,%9}, {%0,%1,%2,%3};"
        : "+f"(d[0]), "+f"(d[1]), "+f"(d[2]), "+f"(d[3])
        : "r"(a[0]), "r"(a[1]), "r"(a[2]), "r"(a[3]), "r"(b0), "r"(b1));
}
__device__ __forceinline__ void ldsm4(uint32_t& r0, uint32_t& r1,
                                      uint32_t& r2, uint32_t& r3, uint32_t a) {
    asm volatile("ldmatrix.sync.aligned.m8n8.x4.shared.b16 {%0,%1,%2,%3}, [%4];"
                 : "=r"(r0), "=r"(r1), "=r"(r2), "=r"(r3) : "r"(a));
}
__device__ __forceinline__ void cpasync16(uint32_t dst, const void* src) {
    asm volatile("cp.async.ca.shared.global [%0], [%1], 16;"
                 :: "r"(dst), "l"(src) : "memory");
}

// ---------------------------------------------------------------------------
// Fused prolog: P = tables@W1_l + b1/8 (FFMA2), W2 transpose, dtype detect.
__global__ void __launch_bounds__(512) precompute_kernel(
        const float* __restrict__ tables, const float* __restrict__ W1,
        const float* __restrict__ b1, const float* __restrict__ W2,
        const unsigned int* __restrict__ hap) {
    __shared__ float4 sT4[16 * 64];     // 16 rows x 256 f32
    __shared__ u64    sTp[8 * 256];     // row-pairs, [q][d]
    const int l  = blockIdx.x >> 5;
    const int v0 = (blockIdx.x & 31) << 4;
    const int j  = threadIdx.x;

    {
        int gidx = blockIdx.x * 512 + j;
        int k = gidx >> 8, n = gidx & 255;
        g_W2T[n * HID_ + k] = __float2half_rn(W2[gidx]);
    }
    if (blockIdx.x == 0 && j == 0) {
        int ok = 1;
        for (int i = 0; i < 64; i++) ok &= (hap[2 * i + 1] == 0u);
        g_is64 = ok;
    }

    const float4* tsrc = (const float4*)(tables + (l * V_ + v0) * D_);
    sT4[j]       = tsrc[j];
    sT4[j + 512] = tsrc[j + 512];
    __syncthreads();
    // repack into row pairs: sTp[q*256+d] = (T[2q][d], T[2q+1][d])
    const float* sTf = (const float*)sT4;
#pragma unroll
    for (int i = 0; i < 4; i++) {
        int e = j + 512 * i;            // 0..2047
        int q = e >> 8, d = e & 255;
        sTp[e] = pack2(sTf[(2 * q) * 256 + d], sTf[(2 * q + 1) * 256 + d]);
    }
    __syncthreads();

    const float b1v = 0.125f * b1[j];
    u64 acc2[8];
#pragma unroll
    for (int q = 0; q < 8; q++) acc2[q] = pack2(b1v, b1v);

    const float* w1p = W1 + (l * D_) * HID_ + j;
#pragma unroll 4
    for (int d2 = 0; d2 < 128; d2++) {
        float w0 = w1p[(2 * d2) * HID_];
        float w1 = w1p[(2 * d2 + 1) * HID_];
        u64 wp0 = pack2(w0, w0);
        u64 wp1 = pack2(w1, w1);
#pragma unroll
        for (int q = 0; q < 8; q++) {
            const u64* tp = sTp + q * 256 + 2 * d2;   // broadcast LDS.128
            u64 a0 = tp[0], a1 = tp[1];
            fma2(acc2[q], a0, wp0);
            fma2(acc2[q], a1, wp1);
        }
    }
#pragma unroll
    for (int q = 0; q < 8; q++) {
        float lo, hi;
        unpack2(acc2[q], lo, hi);
        g_Ph[(l * V_ + v0 + 2 * q) * HID_ + j]     = __float2half_rn(lo);
        g_Ph[(l * V_ + v0 + 2 * q + 1) * HID_ + j] = __float2half_rn(hi);
    }
}

// ---------------------------------------------------------------------------
__global__ void __launch_bounds__(512, 2) main_kernel(
        const unsigned int* __restrict__ hap,
        const float* __restrict__ b2,
        float* __restrict__ out) {
    extern __shared__ char smem[];
    int*    sTok = (int*)(smem + SM_TOK_B);
    __half* sA   = (__half*)(smem + SM_A_B);
    __half* sB   = (__half*)(smem + SM_B_B);
    const uint32_t sbA = (uint32_t)__cvta_generic_to_shared(sA);
    const uint32_t sbB = (uint32_t)__cvta_generic_to_shared(sB);

    const int tid = threadIdx.x, warp = tid >> 5, lane = tid & 31;
    const int is64 = g_is64;

    // tokens (clamped): one per thread
    {
        long gi = (long)blockIdx.x * (MTILE * L_) + tid;
        int v = is64 ? (int)hap[2 * gi] : (int)hap[gi];
        v = v < 0 ? 0 : (v > V_ - 1 ? V_ - 1 : v);
        sTok[tid] = v;
    }

    float acc[2][4][4];
#pragma unroll
    for (int mi = 0; mi < 2; mi++)
#pragma unroll
        for (int q = 0; q < 4; q++)
#pragma unroll
            for (int d = 0; d < 4; d++) acc[mi][q][d] = 0.f;

    // producer: row pm, 16B segment pc
    const int pm = tid >> 3;
    const int pc = tid & 7;
    // consumer: 2m x 8n warps, tile 32x32
    const int m0 = (warp >> 3) * 32;
    const int n0 = (warp & 7) * 32;

    const uint32_t aoff0 = ((uint32_t)(m0 + (lane & 15)) * SAH +
                            (uint32_t)(lane >> 4) * 8) * 2;
    const uint32_t boff0 = ((uint32_t)(n0 + (lane >> 4) * 8 + (lane & 7)) * SBH +
                            (uint32_t)((lane >> 3) & 1) * 8) * 2;

    __syncthreads();

    // tokens packed 2x16b -> 4 regs (chunk-invariant)
    uint32_t tokp[4];
#pragma unroll
    for (int i = 0; i < 4; i++)
        tokp[i] = (uint32_t)sTok[pm * L_ + 2 * i] |
                  ((uint32_t)sTok[pm * L_ + 2 * i + 1] << 16);

    const char* pBc = (const char*)g_Ph + pc * 16;

    // ---------------- producer ----------------
    auto produce = [&](int kt, int buf) {
        const uint32_t kb = (uint32_t)(kt * KCH * 2);
        {   // B tile via cp.async: 4 x 16B per thread
            const uint32_t dstB = sbB + (uint32_t)(buf * SB_BUFH * 2);
            const __half* srcB = g_W2T + kt * KCH + pc * 8;
#pragma unroll
            for (int j = 0; j < 4; j++) {
                int n = (tid >> 3) + j * 64;
                cpasync16(dstB + (uint32_t)(n * SBH + pc * 8) * 2,
                          srcB + n * HID_);
            }
            asm volatile("cp.async.commit_group;" ::: "memory");
        }
        {   // A row-segment: gelu(sum_l P)
            float2 a0 = make_float2(0.f, 0.f), a1 = a0, a2 = a0, a3 = a0;
#pragma unroll
            for (int lp = 0; lp < 4; lp++) {
                const uint4 u = *(const uint4*)(pBc + ((2 * lp) << 19) +
                        ((tokp[lp] & 0xFFFFu) << 10) + kb);
                const uint4 w = *(const uint4*)(pBc + ((2 * lp + 1) << 19) +
                        ((tokp[lp] >> 16) << 10) + kb);
                __half2 t; float2 p;
                t = __hadd2(*(const __half2*)&u.x, *(const __half2*)&w.x);
                p = __half22float2(t); a0.x += p.x; a0.y += p.y;
                t = __hadd2(*(const __half2*)&u.y, *(const __half2*)&w.y);
                p = __half22float2(t); a1.x += p.x; a1.y += p.y;
                t = __hadd2(*(const __half2*)&u.z, *(const __half2*)&w.z);
                p = __half22float2(t); a2.x += p.x; a2.y += p.y;
                t = __hadd2(*(const __half2*)&u.w, *(const __half2*)&w.w);
                p = __half22float2(t); a3.x += p.x; a3.y += p.y;
            }
            __half2 h0 = __floats2half2_rn(gelu_fast(a0.x), gelu_fast(a0.y));
            __half2 h1 = __floats2half2_rn(gelu_fast(a1.x), gelu_fast(a1.y));
            __half2 h2 = __floats2half2_rn(gelu_fast(a2.x), gelu_fast(a2.y));
            __half2 h3 = __floats2half2_rn(gelu_fast(a3.x), gelu_fast(a3.y));
            uint4 pk;
            pk.x = *(uint32_t*)&h0; pk.y = *(uint32_t*)&h1;
            pk.z = *(uint32_t*)&h2; pk.w = *(uint32_t*)&h3;
            *(uint4*)(sA + buf * SA_BUFH + pm * SAH + pc * 8) = pk;
        }
    };

    // ---------------- consumer: 32x32 tile ----------------
    auto consume = [&](int buf) {
        const uint32_t aB = sbA + (uint32_t)(buf * SA_BUFH * 2) + aoff0;
        const uint32_t bB = sbB + (uint32_t)(buf * SB_BUFH * 2) + boff0;
#pragma unroll
        for (int ks = 0; ks < 4; ks++) {
            uint32_t a[8];
            ldsm4(a[0], a[1], a[2], a[3], aB + (uint32_t)(ks * 32));
            ldsm4(a[4], a[5], a[6], a[7],
                  aB + (uint32_t)(16 * SAH * 2) + (uint32_t)(ks * 32));
#pragma unroll
            for (int jn = 0; jn < 2; jn++) {
                uint32_t b0, b1r, b2r, b3r;
                ldsm4(b0, b1r, b2r, b3r,
                      bB + (uint32_t)(jn * 16 * SBH * 2) + (uint32_t)(ks * 32));
                mma_f16(acc[0][2 * jn],     a,     b0, b1r);
                mma_f16(acc[1][2 * jn],     a + 4, b0, b1r);
                mma_f16(acc[0][2 * jn + 1], a,     b2r, b3r);
                mma_f16(acc[1][2 * jn + 1], a + 4, b2r, b3r);
            }
        }
    };

    // ---------------- pipeline ----------------
    produce(0, 0);
    asm volatile("cp.async.wait_group 0;" ::: "memory");
    __syncthreads();
#pragma unroll 1
    for (int kt = 0; kt < NCH; kt++) {
        const int buf = kt & 1;
        if (kt + 1 < NCH) produce(kt + 1, buf ^ 1);
        consume(buf);
        asm volatile("cp.async.wait_group 0;" ::: "memory");
        __syncthreads();
    }

    // ---------------- epilogue: + b2, store ----------------
    const float2* b2p = (const float2*)b2;
    float2* o2 = (float2*)out;
#pragma unroll
    for (int mi = 0; mi < 2; mi++) {
        size_t r0 = (size_t)blockIdx.x * MTILE + m0 + mi * 16 + (lane >> 2);
#pragma unroll
        for (int q = 0; q < 4; q++) {
            int cc = n0 / 2 + 4 * q + (lane & 3);
            float2 bv = __ldg(&b2p[cc]);
            float2 v0 = make_float2(acc[mi][q][0] + bv.x, acc[mi][q][1] + bv.y);
            float2 v1 = make_float2(acc[mi][q][2] + bv.x, acc[mi][q][3] + bv.y);
            o2[r0 * 128 + cc]       = v0;
            o2[(r0 + 8) * 128 + cc] = v1;
        }
    }
}

// ---------------------------------------------------------------------------
extern "C" void kernel_launch(void* const* d_in, const int* in_sizes, int n_in,
                              void* d_out, int out_size) {
    const unsigned int* hap    = (const unsigned int*)d_in[0];
    const float*        tables = (const float*)d_in[1];
    const float*        W1     = (const float*)d_in[2];
    const float*        b1     = (const float*)d_in[3];
    const float*        W2     = (const float*)d_in[4];
    const float*        b2     = (const float*)d_in[5];
    float*              out    = (float*)d_out;

    cudaFuncSetAttribute(main_kernel,
                         cudaFuncAttributeMaxDynamicSharedMemorySize, SMEM_BYTES);

    precompute_kernel<<<L_ * 32, 512>>>(tables, W1, b1, W2, hap);
    main_kernel<<<NBLK, 512, SMEM_BYTES>>>(hap, b2, out);
}

// round 10
// speedup vs baseline: 1.2434x; 1.1829x over previous
#include <cuda_runtime.h>
#include <cuda_fp16.h>
#include <math.h>
#include <stdint.h>

// ---------------------------------------------------------------------------
// HaplotypeEmbedding, fp16 + mma.sync m16n8k16 + ldmatrix.
// r6 configuration (256 thr, MTILE 64, warp tile 32x64, occ 2) +
// cp.async B staging + b1 folded into P + branchless gelu.
// ---------------------------------------------------------------------------

#define L_    8
#define V_    512
#define D_    256
#define HID_  512
#define NOUT_ 256
#define NTOT  131072
#define MTILE 64
#define NBLK  (NTOT / MTILE)   // 2048
#define KCH   64
#define NCH   (HID_ / KCH)     // 8

#define SAH 72
#define SBH 72
#define SA_BUFH (MTILE * SAH)   // 4608 halves
#define SB_BUFH (NOUT_ * SBH)   // 18432 halves

#define SM_TOK_B 0
#define SM_A_B   2048
#define SM_B_B   (SM_A_B + 2 * SA_BUFH * 2)     // 20480
#define SMEM_BYTES (SM_B_B + 2 * SB_BUFH * 2)   // 94208

__device__ __half g_Ph[L_ * V_ * HID_];
__device__ __half g_W2T[NOUT_ * HID_];
__device__ int    g_is64;

typedef unsigned long long u64;
__device__ __forceinline__ u64 pack2(float lo, float hi) {
    u64 r; asm("mov.b64 %0, {%1, %2};" : "=l"(r) : "f"(lo), "f"(hi)); return r;
}
__device__ __forceinline__ void unpack2(u64 v, float& lo, float& hi) {
    asm("mov.b64 {%0, %1}, %2;" : "=f"(lo), "=f"(hi) : "l"(v));
}
__device__ __forceinline__ void fma2(u64& c, u64 a, u64 b) {
    asm("fma.rn.f32x2 %0, %1, %2, %0;" : "+l"(c) : "l"(a), "l"(b));
}
__device__ __forceinline__ float gelu_fast(float x) {
    float ax = fabsf(x);
    float z  = 0.70710678118f * ax;
    float t  = __fdividef(1.0f, fmaf(0.47047f, z, 1.0f));
    float q  = fmaf(fmaf(0.7478556f, t, -0.0958798f), t, 0.3480242f) * t;
    float e  = __expf(-z * z);
    float er = fmaf(-q, e, 1.0f);
    return fmaf(0.5f * ax, er, 0.5f * x);
}
__device__ __forceinline__ void mma_f16(float* d, const uint32_t* a,
                                        uint32_t b0, uint32_t b1) {
    asm volatile(
        "mma.sync.aligned.m16n8k16.row.col.f32.f16.f16.f32 "
        "{%0,%1,%2,%3}, {%4,%5,%6,%7}, {%8,%9}, {%0,%1,%2,%3};"
        : "+f"(d[0]), "+f"(d[1]), "+f"(d[2]), "+f"(d[3])
        : "r"(a[0]), "r"(a[1]), "r"(a[2]), "r"(a[3]), "r"(b0), "r"(b1));
}
__device__ __forceinline__ void ldsm4(uint32_t& r0, uint32_t& r1,
                                      uint32_t& r2, uint32_t& r3, uint32_t a) {
    asm volatile("ldmatrix.sync.aligned.m8n8.x4.shared.b16 {%0,%1,%2,%3}, [%4];"
                 : "=r"(r0), "=r"(r1), "=r"(r2), "=r"(r3) : "r"(a));
}
__device__ __forceinline__ void cpasync16(uint32_t dst, const void* src) {
    asm volatile("cp.async.ca.shared.global [%0], [%1], 16;"
                 :: "r"(dst), "l"(src) : "memory");
}

// ---------------------------------------------------------------------------
// Fused prolog: P = tables@W1_l + b1/8 (FFMA2), W2 transpose, dtype detect.
__global__ void __launch_bounds__(512) precompute_kernel(
        const float* __restrict__ tables, const float* __restrict__ W1,
        const float* __restrict__ b1, const float* __restrict__ W2,
        const unsigned int* __restrict__ hap) {
    __shared__ float4 sT4[16 * 64];
    __shared__ u64    sTp[8 * 256];
    const int l  = blockIdx.x >> 5;
    const int v0 = (blockIdx.x & 31) << 4;
    const int j  = threadIdx.x;

    {
        int gidx = blockIdx.x * 512 + j;
        int k = gidx >> 8, n = gidx & 255;
        g_W2T[n * HID_ + k] = __float2half_rn(W2[gidx]);
    }
    if (blockIdx.x == 0 && j == 0) {
        int ok = 1;
        for (int i = 0; i < 64; i++) ok &= (hap[2 * i + 1] == 0u);
        g_is64 = ok;
    }

    const float4* tsrc = (const float4*)(tables + (l * V_ + v0) * D_);
    sT4[j]       = tsrc[j];
    sT4[j + 512] = tsrc[j + 512];
    __syncthreads();
    const float* sTf = (const float*)sT4;
#pragma unroll
    for (int i = 0; i < 4; i++) {
        int e = j + 512 * i;
        int q = e >> 8, d = e & 255;
        sTp[e] = pack2(sTf[(2 * q) * 256 + d], sTf[(2 * q + 1) * 256 + d]);
    }
    __syncthreads();

    const float b1v = 0.125f * b1[j];
    u64 acc2[8];
#pragma unroll
    for (int q = 0; q < 8; q++) acc2[q] = pack2(b1v, b1v);

    const float* w1p = W1 + (l * D_) * HID_ + j;
#pragma unroll 4
    for (int d2 = 0; d2 < 128; d2++) {
        float w0 = w1p[(2 * d2) * HID_];
        float w1 = w1p[(2 * d2 + 1) * HID_];
        u64 wp0 = pack2(w0, w0);
        u64 wp1 = pack2(w1, w1);
#pragma unroll
        for (int q = 0; q < 8; q++) {
            const u64* tp = sTp + q * 256 + 2 * d2;
            u64 a0 = tp[0], a1 = tp[1];
            fma2(acc2[q], a0, wp0);
            fma2(acc2[q], a1, wp1);
        }
    }
#pragma unroll
    for (int q = 0; q < 8; q++) {
        float lo, hi;
        unpack2(acc2[q], lo, hi);
        g_Ph[(l * V_ + v0 + 2 * q) * HID_ + j]     = __float2half_rn(lo);
        g_Ph[(l * V_ + v0 + 2 * q + 1) * HID_ + j] = __float2half_rn(hi);
    }
}

// ---------------------------------------------------------------------------
__global__ void __launch_bounds__(256, 2) main_kernel(
        const unsigned int* __restrict__ hap,
        const float* __restrict__ b2,
        float* __restrict__ out) {
    extern __shared__ char smem[];
    int*    sTok = (int*)(smem + SM_TOK_B);
    __half* sA   = (__half*)(smem + SM_A_B);
    __half* sB   = (__half*)(smem + SM_B_B);
    const uint32_t sbA = (uint32_t)__cvta_generic_to_shared(sA);
    const uint32_t sbB = (uint32_t)__cvta_generic_to_shared(sB);

    const int tid = threadIdx.x, warp = tid >> 5, lane = tid & 31;
    const int is64 = g_is64;

    // tokens (clamped)
    {
        long gbase = (long)blockIdx.x * (MTILE * L_);
#pragma unroll
        for (int i = 0; i < 2; i++) {
            int idx = tid + 256 * i;
            long gi = gbase + idx;
            int v = is64 ? (int)hap[2 * gi] : (int)hap[gi];
            v = v < 0 ? 0 : (v > V_ - 1 ? V_ - 1 : v);
            sTok[idx] = v;
        }
    }

    float acc[2][8][4];
#pragma unroll
    for (int mt = 0; mt < 2; mt++)
#pragma unroll
        for (int j = 0; j < 8; j++)
#pragma unroll
            for (int q = 0; q < 4; q++) acc[mt][j][q] = 0.f;

    const int c  = lane & 7;            // 16B segment (producer)
    const int r  = lane >> 3;           // row sub-index (producer)
    const int m0 = (warp >> 2) * 32;    // consumer row base
    const int n0 = (warp & 3) * 64;     // consumer col base
    const int bn = tid >> 3;            // B-stage row (0..31)
    const int bc = tid & 7;

    const uint32_t aoff0 = ((uint32_t)(m0 + ((lane >> 3) & 1) * 8 + (lane & 7)) * SAH +
                            (uint32_t)(lane >> 4) * 8) * 2;
    const uint32_t boff0 = ((uint32_t)(n0 + (lane >> 4) * 8 + (lane & 7)) * SBH +
                            (uint32_t)((lane >> 3) & 1) * 8) * 2;

    __syncthreads();

    // ---------------- producer ----------------
    auto produce = [&](int kt, int buf) {
        const int k0 = kt * KCH;
        {   // B tile via cp.async: 8 x 16B per thread
            const uint32_t dstB = sbB + (uint32_t)(buf * SB_BUFH * 2);
            const __half* srcB = g_W2T + k0 + bc * 8;
#pragma unroll
            for (int i = 0; i < 8; i++) {
                int n = bn + i * 32;
                cpasync16(dstB + (uint32_t)(n * SBH + bc * 8) * 2,
                          srcB + n * HID_);
            }
            asm volatile("cp.async.commit_group;" ::: "memory");
        }
        __half* A = sA + buf * SA_BUFH;
#pragma unroll
        for (int it = 0; it < 2; it++) {
            int m = it * 32 + warp * 4 + r;
            const int* tk = sTok + m * L_;
            float2 a0 = make_float2(0.f, 0.f), a1 = a0, a2 = a0, a3 = a0;
#pragma unroll
            for (int lp = 0; lp < 4; lp++) {
                const uint4 u = *(const uint4*)(g_Ph +
                        (((2 * lp) * V_ + tk[2 * lp]) << 9) + k0 + c * 8);
                const uint4 w = *(const uint4*)(g_Ph +
                        (((2 * lp + 1) * V_ + tk[2 * lp + 1]) << 9) + k0 + c * 8);
                __half2 t; float2 p;
                t = __hadd2(*(const __half2*)&u.x, *(const __half2*)&w.x);
                p = __half22float2(t); a0.x += p.x; a0.y += p.y;
                t = __hadd2(*(const __half2*)&u.y, *(const __half2*)&w.y);
                p = __half22float2(t); a1.x += p.x; a1.y += p.y;
                t = __hadd2(*(const __half2*)&u.z, *(const __half2*)&w.z);
                p = __half22float2(t); a2.x += p.x; a2.y += p.y;
                t = __hadd2(*(const __half2*)&u.w, *(const __half2*)&w.w);
                p = __half22float2(t); a3.x += p.x; a3.y += p.y;
            }
            __half2 h0 = __floats2half2_rn(gelu_fast(a0.x), gelu_fast(a0.y));
            __half2 h1 = __floats2half2_rn(gelu_fast(a1.x), gelu_fast(a1.y));
            __half2 h2 = __floats2half2_rn(gelu_fast(a2.x), gelu_fast(a2.y));
            __half2 h3 = __floats2half2_rn(gelu_fast(a3.x), gelu_fast(a3.y));
            uint4 pk;
            pk.x = *(uint32_t*)&h0; pk.y = *(uint32_t*)&h1;
            pk.z = *(uint32_t*)&h2; pk.w = *(uint32_t*)&h3;
            *(uint4*)(A + m * SAH + c * 8) = pk;
        }
    };

    // ---------------- consumer: warp tile 32x64 ----------------
    auto consume = [&](int buf) {
        const uint32_t aB = sbA + (uint32_t)(buf * SA_BUFH * 2) + aoff0;
        const uint32_t bB = sbB + (uint32_t)(buf * SB_BUFH * 2) + boff0;
#pragma unroll
        for (int ks = 0; ks < 4; ks++) {
            uint32_t a[2][4];
#pragma unroll
            for (int mt = 0; mt < 2; mt++)
                ldsm4(a[mt][0], a[mt][1], a[mt][2], a[mt][3],
                      aB + (uint32_t)(mt * 16 * SAH * 2) + (uint32_t)(ks * 32));
#pragma unroll
            for (int jp = 0; jp < 4; jp++) {
                uint32_t b0, b1r, b2r, b3r;
                ldsm4(b0, b1r, b2r, b3r,
                      bB + (uint32_t)(jp * 16 * SBH * 2) + (uint32_t)(ks * 32));
                mma_f16(acc[0][2 * jp],     a[0], b0, b1r);
                mma_f16(acc[1][2 * jp],     a[1], b0, b1r);
                mma_f16(acc[0][2 * jp + 1], a[0], b2r, b3r);
                mma_f16(acc[1][2 * jp + 1], a[1], b2r, b3r);
            }
        }
    };

    // ---------------- pipeline ----------------
    produce(0, 0);
    asm volatile("cp.async.wait_group 0;" ::: "memory");
    __syncthreads();
#pragma unroll 1
    for (int kt = 0; kt < NCH; kt++) {
        const int buf = kt & 1;
        if (kt + 1 < NCH) produce(kt + 1, buf ^ 1);
        consume(buf);
        asm volatile("cp.async.wait_group 0;" ::: "memory");
        __syncthreads();
    }

    // ---------------- epilogue: + b2, store ----------------
    const float2* b2p = (const float2*)b2;
    float2* o2 = (float2*)out;
#pragma unroll
    for (int mt = 0; mt < 2; mt++) {
        size_t r0 = (size_t)blockIdx.x * MTILE + m0 + mt * 16 + (lane >> 2);
#pragma unroll
        for (int j = 0; j < 8; j++) {
            int cc = n0 / 2 + 4 * j + (lane & 3);
            float2 bv = __ldg(&b2p[cc]);
            float2 v0 = make_float2(acc[mt][j][0] + bv.x,
                                    acc[mt][j][1] + bv.y);
            float2 v1 = make_float2(acc[mt][j][2] + bv.x,
                                    acc[mt][j][3] + bv.y);
            o2[r0 * 128 + cc]       = v0;
            o2[(r0 + 8) * 128 + cc] = v1;
        }
    }
}

// ---------------------------------------------------------------------------
extern "C" void kernel_launch(void* const* d_in, const int* in_sizes, int n_in,
                              void* d_out, int out_size) {
    const unsigned int* hap    = (const unsigned int*)d_in[0];
    const float*        tables = (const float*)d_in[1];
    const float*        W1     = (const float*)d_in[2];
    const float*        b1     = (const float*)d_in[3];
    const float*        W2     = (const float*)d_in[4];
    const float*        b2     = (const float*)d_in[5];
    float*              out    = (float*)d_out;

    cudaFuncSetAttribute(main_kernel,
                         cudaFuncAttributeMaxDynamicSharedMemorySize, SMEM_BYTES);

    precompute_kernel<<<L_ * 32, 512>>>(tables, W1, b1, W2, hap);
    main_kernel<<<NBLK, 256, SMEM_BYTES>>>(hap, b2, out);
}